// round 6
// baseline (speedup 1.0000x reference)
#include <cuda_runtime.h>
#include <cuda_bf16.h>
#include <math.h>

#define N_NODES 50000
#define N_EDGES 1600000
#define IN_F 128
#define OUT_F 64
#define LRELU_ALPHA 0.2f
#define EXP_CLAMP 1000000.0f
#define DENOM_EPS 1e-10f

#define SCAN_B 1024
#define SCAN_NBLK ((N_NODES + SCAN_B - 1) / SCAN_B)   // 49

// ---- scratch (device globals: no allocation allowed) ----
__device__ float g_Wh[N_NODES * OUT_F];
__device__ float g_s[N_NODES];
__device__ float g_t[N_NODES];
__device__ int   g_cnt[N_NODES];
__device__ int   g_start[N_NODES];
__device__ int   g_cursor[N_NODES];
__device__ int   g_esrc[N_EDGES];
__device__ int   g_blocksum[SCAN_NBLK];
__device__ int   g_blockpref[SCAN_NBLK];
__device__ int   g_mode64;   // 1 if adj is int64, 0 if int32

__device__ __forceinline__ int clamp_node(int v) {
    return min(max(v, 0), N_NODES - 1);
}

// Fetch edge e as (dst, src) under either adj dtype.
__device__ __forceinline__ int2 load_edge(const int* __restrict__ adj, int e, int mode64) {
    int2 r;
    if (mode64) {
        // int64 pairs: dst at word 4e, src at word 4e+2 (low halves)
        r.x = adj[4 * (size_t)e];
        r.y = adj[4 * (size_t)e + 2];
    } else {
        r = reinterpret_cast<const int2*>(adj)[e];
    }
    r.x = clamp_node(r.x);
    r.y = clamp_node(r.y);
    return r;
}

// ---------------------------------------------------------------------------
// K-1: detect adj dtype. Odd int32 words in the first 512B are high halves
// (all zero) iff adj is int64; for int32 pairs they are random src ids.
// ---------------------------------------------------------------------------
__global__ void k_detect(const int* __restrict__ adj) {
    int t = threadIdx.x;                 // 64 threads
    int v = adj[2 * t + 1];
#pragma unroll
    for (int off = 16; off > 0; off >>= 1)
        v |= __shfl_xor_sync(0xffffffffu, v, off);
    __shared__ int sv[2];
    if ((t & 31) == 0) sv[t >> 5] = v;
    __syncthreads();
    if (t == 0) g_mode64 = ((sv[0] | sv[1]) == 0) ? 1 : 0;
}

// ---------------------------------------------------------------------------
// K0: zero histogram counters
// ---------------------------------------------------------------------------
__global__ void k_zero() {
    int i = blockIdx.x * blockDim.x + threadIdx.x;
    if (i < N_NODES) g_cnt[i] = 0;
}

// ---------------------------------------------------------------------------
// K1: Wh = h @ W  (fused s = Wh*a1, t = Wh*a2)
// One warp per node row; lane handles cols (lane, lane+32).
// ---------------------------------------------------------------------------
__global__ __launch_bounds__(256) void k_gemm(const float* __restrict__ h,
                                              const float* __restrict__ W,
                                              const float* __restrict__ a) {
    __shared__ float sW[IN_F * OUT_F];   // 32KB
    __shared__ float sh[8][IN_F];        // 4KB

    int tid  = threadIdx.x;
    int wid  = tid >> 5;
    int lane = tid & 31;

    for (int i = tid; i < IN_F * OUT_F; i += 256) sW[i] = W[i];

    int row = blockIdx.x * 8 + wid;
    if (row < N_NODES) {
        float4 hv = reinterpret_cast<const float4*>(h + (size_t)row * IN_F)[lane];
        sh[wid][lane * 4 + 0] = hv.x;
        sh[wid][lane * 4 + 1] = hv.y;
        sh[wid][lane * 4 + 2] = hv.z;
        sh[wid][lane * 4 + 3] = hv.w;
    }
    __syncthreads();

    if (row >= N_NODES) return;

    float wh0 = 0.0f, wh1 = 0.0f;
    const float* hr = sh[wid];
#pragma unroll 8
    for (int k = 0; k < IN_F; k++) {
        float hk = hr[k];
        wh0 = fmaf(hk, sW[k * OUT_F + lane],      wh0);
        wh1 = fmaf(hk, sW[k * OUT_F + lane + 32], wh1);
    }

    g_Wh[(size_t)row * OUT_F + lane]      = wh0;
    g_Wh[(size_t)row * OUT_F + lane + 32] = wh1;

    float ps = wh0 * a[lane]      + wh1 * a[lane + 32];
    float pt = wh0 * a[64 + lane] + wh1 * a[64 + lane + 32];
#pragma unroll
    for (int off = 16; off > 0; off >>= 1) {
        ps += __shfl_down_sync(0xffffffffu, ps, off);
        pt += __shfl_down_sync(0xffffffffu, pt, off);
    }
    if (lane == 0) {
        g_s[row] = ps;
        g_t[row] = pt;
    }
}

// ---------------------------------------------------------------------------
// K2: histogram of destination degrees
// ---------------------------------------------------------------------------
__global__ __launch_bounds__(256) void k_hist(const int* __restrict__ adj) {
    int e = blockIdx.x * blockDim.x + threadIdx.x;
    if (e >= N_EDGES) return;
    int mode64 = g_mode64;
    int2 p = load_edge(adj, e, mode64);
    atomicAdd(&g_cnt[p.x], 1);
}

// ---------------------------------------------------------------------------
// K3a/K3b/K3c: exclusive prefix sum of g_cnt -> g_start (and g_cursor copy)
// ---------------------------------------------------------------------------
__global__ __launch_bounds__(SCAN_B) void k_scan1() {
    __shared__ int sdata[SCAN_B];
    int t = threadIdx.x;
    int i = blockIdx.x * SCAN_B + t;
    int v = (i < N_NODES) ? g_cnt[i] : 0;
    sdata[t] = v;
    __syncthreads();
#pragma unroll
    for (int off = 1; off < SCAN_B; off <<= 1) {
        int x = (t >= off) ? sdata[t - off] : 0;
        __syncthreads();
        sdata[t] += x;
        __syncthreads();
    }
    if (i < N_NODES) g_start[i] = sdata[t];          // inclusive, fixed in K3c
    if (t == SCAN_B - 1) g_blocksum[blockIdx.x] = sdata[t];
}

__global__ void k_scan2() {
    if (threadIdx.x == 0 && blockIdx.x == 0) {
        int running = 0;
        for (int b = 0; b < SCAN_NBLK; b++) {
            g_blockpref[b] = running;
            running += g_blocksum[b];
        }
    }
}

__global__ void k_scan3() {
    int i = blockIdx.x * blockDim.x + threadIdx.x;
    if (i >= N_NODES) return;
    int incl = g_start[i];
    int st = incl - g_cnt[i] + g_blockpref[i >> 10];
    g_start[i]  = st;
    g_cursor[i] = st;
}

// ---------------------------------------------------------------------------
// K4: place edges into CSR order (counting sort scatter)
// ---------------------------------------------------------------------------
__global__ __launch_bounds__(256) void k_place(const int* __restrict__ adj) {
    int e = blockIdx.x * blockDim.x + threadIdx.x;
    if (e >= N_EDGES) return;
    int mode64 = g_mode64;
    int2 p = load_edge(adj, e, mode64);
    int pos = atomicAdd(&g_cursor[p.x], 1);
    pos = min(max(pos, 0), N_EDGES - 1);   // insurance
    g_esrc[pos] = p.y;
}

// ---------------------------------------------------------------------------
// K5: single-pass gather-aggregate. One warp per destination node.
// Per 32-edge chunk: lane i loads src_i (coalesced), computes its own
// x_i = clip(exp(lrelu(s_v + t[src_i]))) (exp parallel across lanes),
// accumulates dsum locally; inner loop broadcasts (src_j, x_j) and all lanes
// accumulate x_j * Wh[src_j][lane(,+32)] — two coalesced 128B lines/edge.
// denom division deferred to the end (acc is linear in x).
// ---------------------------------------------------------------------------
__global__ __launch_bounds__(256) void k_agg(float* __restrict__ out) {
    int v = blockIdx.x * 8 + (threadIdx.x >> 5);
    int lane = threadIdx.x & 31;
    if (v >= N_NODES) return;

    int beg = g_start[v];
    int n   = g_cnt[v];
    float sv = g_s[v];

    float dsum = 0.0f;
    float acc0 = 0.0f, acc1 = 0.0f;

    for (int base = 0; base < n; base += 32) {
        int m = n - base;
        if (m > 32) m = 32;

        // parallel phase: per-lane edge weight
        int src = 0;
        float x = 0.0f;
        if (lane < m) {
            src = g_esrc[beg + base + lane];
            float ev = sv + g_t[src];
            ev = ev > 0.0f ? ev : LRELU_ALPHA * ev;
            x = fminf(__expf(ev), EXP_CLAMP);
        }
        dsum += x;

        // broadcast phase: accumulate weighted Wh rows
        for (int j = 0; j < m; j++) {
            int   sj = __shfl_sync(0xffffffffu, src, j);
            float xj = __shfl_sync(0xffffffffu, x,   j);
            const float* wr = g_Wh + (size_t)sj * OUT_F;
            acc0 = fmaf(xj, wr[lane],      acc0);
            acc1 = fmaf(xj, wr[lane + 32], acc1);
        }
    }

#pragma unroll
    for (int off = 16; off > 0; off >>= 1)
        dsum += __shfl_xor_sync(0xffffffffu, dsum, off);
    float inv_denom = 1.0f / (dsum + DENOM_EPS);

    acc0 *= inv_denom;
    acc1 *= inv_denom;
    acc0 = acc0 > 0.0f ? acc0 : expm1f(acc0);
    acc1 = acc1 > 0.0f ? acc1 : expm1f(acc1);
    out[(size_t)v * OUT_F + lane]      = acc0;
    out[(size_t)v * OUT_F + lane + 32] = acc1;
}

extern "C" void kernel_launch(void* const* d_in, const int* in_sizes, int n_in,
                              void* d_out, int out_size) {
    const float* h   = (const float*)d_in[0];
    const float* W   = (const float*)d_in[1];
    const float* a   = (const float*)d_in[2];
    const int*   adj = (const int*)d_in[3];
    float* out = (float*)d_out;

    k_detect<<<1, 64>>>(adj);
    k_zero<<<(N_NODES + 255) / 256, 256>>>();
    k_gemm<<<(N_NODES + 7) / 8, 256>>>(h, W, a);
    k_hist<<<(N_EDGES + 255) / 256, 256>>>(adj);
    k_scan1<<<SCAN_NBLK, SCAN_B>>>();
    k_scan2<<<1, 32>>>();
    k_scan3<<<(N_NODES + 255) / 256, 256>>>();
    k_place<<<(N_EDGES + 255) / 256, 256>>>(adj);
    k_agg<<<(N_NODES + 7) / 8, 256>>>(out);
}